// round 6
// baseline (speedup 1.0000x reference)
#include <cuda_runtime.h>
#include <math.h>

#define Hdim   1024
#define H2     512
#define Cdim   256
#define Msize  100000
#define Nsamp  1024
#define Tlen   1024
#define G3     3072
#define REC_CTAS 128
#define UPC    8            // hidden units per CTA (one per warp)

// ---------------- scratch (static __device__, no allocs) ----------------
__device__ __align__(16) float d_samples[Nsamp * Hdim];
__device__ __align__(16) float d_e1[Nsamp * H2];
__device__ __align__(16) float d_encoded[Nsamp * H2];
__device__ __align__(16) float d_zbuf[Nsamp * Cdim];
__device__ __align__(16) float d_d1[Nsamp * H2];
__device__ __align__(16) float d_recon[Nsamp * Hdim];
__device__ __align__(16) float d_gx[Tlen * G3];
__device__ __align__(16) float d_y1[Tlen * Hdim];
__device__ __align__(16) float d_wout[Tlen * Hdim];
__device__ float d_toterr[Nsamp];
__device__ __align__(16) float g_h[2][Hdim];
// 4-sharded per-step counters; shards 128B apart ([t][shard*8])
__device__ __align__(128) unsigned g_cnt[2 * Tlen][32];

__device__ __forceinline__ float gelu_exact(float x) {
    return 0.5f * x * (1.0f + erff(x * 0.7071067811865476f));
}
__device__ __forceinline__ float sigmoidf_(float x) {
    return 1.0f / (1.0f + expf(-x));
}
__device__ __forceinline__ void atom_add_release(unsigned* p, unsigned v) {
    unsigned old;
    asm volatile("atom.add.release.gpu.global.u32 %0, [%1], %2;"
                 : "=r"(old) : "l"(p), "r"(v) : "memory");
}
__device__ __forceinline__ unsigned ld_acquire(const unsigned* p) {
    unsigned v;
    asm volatile("ld.acquire.gpu.global.u32 %0, [%1];" : "=r"(v) : "l"(p) : "memory");
    return v;
}

// ---------------- init / small utility kernels ----------------
__global__ void init_kernel() {
    int i = blockIdx.x * blockDim.x + threadIdx.x;    // 256 x 256 = 65536
    if (i < 2 * Tlen * 32) ((unsigned*)g_cnt)[i] = 0u;
    if (i < 2 * Hdim) ((float*)g_h)[i] = 0.0f;
}

__global__ void zero_h_kernel() {
    int i = blockIdx.x * blockDim.x + threadIdx.x;
    if (i < Hdim) g_h[0][i] = 0.0f;
}

__global__ void gather_kernel(const float* __restrict__ mem, const int* __restrict__ idx) {
    int n = blockIdx.x;                               // 1024 blocks, 256 threads
    const float4* src = (const float4*)(mem + (size_t)idx[n] * Hdim);
    float4* dst = (float4*)(d_samples + (size_t)n * Hdim);
    dst[threadIdx.x] = src[threadIdx.x];
}

// ---------------- SGEMM: C[M,N] = A[M,K] @ W[N,K]^T + bias ----------------
#define BM 64
#define BN 64
#define BK 16
__global__ void sgemm_bias_kernel(const float* __restrict__ A, const float* __restrict__ W,
                                  const float* __restrict__ bias, float* __restrict__ C,
                                  int M, int N, int K) {
    __shared__ float As[BK][BM + 4];
    __shared__ float Bs[BK][BN + 4];
    const int tid = threadIdx.x;                      // 256
    const int tx = tid & 15, ty = tid >> 4;
    const int row0 = blockIdx.y * BM, col0 = blockIdx.x * BN;
    const int lm = tid >> 2, lk = (tid & 3) * 4;
    const float* Ap = A + (size_t)(row0 + lm) * K + lk;
    const float* Wp = W + (size_t)(col0 + lm) * K + lk;
    float acc[4][4];
#pragma unroll
    for (int i = 0; i < 4; i++)
#pragma unroll
        for (int j = 0; j < 4; j++) acc[i][j] = 0.0f;

    for (int k0 = 0; k0 < K; k0 += BK) {
        float4 a = *(const float4*)(Ap + k0);
        float4 w = *(const float4*)(Wp + k0);
        __syncthreads();
        As[lk + 0][lm] = a.x; As[lk + 1][lm] = a.y; As[lk + 2][lm] = a.z; As[lk + 3][lm] = a.w;
        Bs[lk + 0][lm] = w.x; Bs[lk + 1][lm] = w.y; Bs[lk + 2][lm] = w.z; Bs[lk + 3][lm] = w.w;
        __syncthreads();
#pragma unroll
        for (int k = 0; k < BK; k++) {
            float4 av = *(const float4*)&As[k][ty * 4];
            float4 bv = *(const float4*)&Bs[k][tx * 4];
            acc[0][0] += av.x * bv.x; acc[0][1] += av.x * bv.y; acc[0][2] += av.x * bv.z; acc[0][3] += av.x * bv.w;
            acc[1][0] += av.y * bv.x; acc[1][1] += av.y * bv.y; acc[1][2] += av.y * bv.z; acc[1][3] += av.y * bv.w;
            acc[2][0] += av.z * bv.x; acc[2][1] += av.z * bv.y; acc[2][2] += av.z * bv.z; acc[2][3] += av.z * bv.w;
            acc[3][0] += av.w * bv.x; acc[3][1] += av.w * bv.y; acc[3][2] += av.w * bv.z; acc[3][3] += av.w * bv.w;
        }
    }
    float b0 = bias[col0 + tx * 4 + 0];
    float b1 = bias[col0 + tx * 4 + 1];
    float b2 = bias[col0 + tx * 4 + 2];
    float b3 = bias[col0 + tx * 4 + 3];
#pragma unroll
    for (int i = 0; i < 4; i++) {
        float* Cr = C + (size_t)(row0 + ty * 4 + i) * N + col0 + tx * 4;
        Cr[0] = acc[i][0] + b0;
        Cr[1] = acc[i][1] + b1;
        Cr[2] = acc[i][2] + b2;
        Cr[3] = acc[i][3] + b3;
    }
}

// ---------------- LayerNorm(512) + exact GELU, in place ----------------
__global__ void ln_gelu_kernel(float* __restrict__ x, const float* __restrict__ g,
                               const float* __restrict__ b) {
    int row = blockIdx.x, tid = threadIdx.x;          // 128 threads, 4 elems each
    float4* xr = (float4*)(x + (size_t)row * H2);
    float4 v = xr[tid];
    float s = v.x + v.y + v.z + v.w;
    __shared__ float red[8];
#pragma unroll
    for (int o = 16; o > 0; o >>= 1) s += __shfl_xor_sync(0xffffffffu, s, o);
    if ((tid & 31) == 0) red[tid >> 5] = s;
    __syncthreads();
    float mean = (red[0] + red[1] + red[2] + red[3]) * (1.0f / 512.0f);
    float dx = v.x - mean, dy = v.y - mean, dz = v.z - mean, dw = v.w - mean;
    float q = dx * dx + dy * dy + dz * dz + dw * dw;
#pragma unroll
    for (int o = 16; o > 0; o >>= 1) q += __shfl_xor_sync(0xffffffffu, q, o);
    if ((tid & 31) == 0) red[4 + (tid >> 5)] = q;
    __syncthreads();
    float var = (red[4] + red[5] + red[6] + red[7]) * (1.0f / 512.0f);
    float rstd = rsqrtf(var + 1e-5f);
    float4 gg = ((const float4*)g)[tid];
    float4 bb = ((const float4*)b)[tid];
    v.x = gelu_exact(dx * rstd * gg.x + bb.x);
    v.y = gelu_exact(dy * rstd * gg.y + bb.y);
    v.z = gelu_exact(dz * rstd * gg.z + bb.z);
    v.w = gelu_exact(dw * rstd * gg.w + bb.w);
    xr[tid] = v;
}

// ---------------- reparameterize ----------------
__global__ void reparam_kernel(const float* __restrict__ eps) {
    int i = blockIdx.x * blockDim.x + threadIdx.x;    // N*C = 262144
    if (i < Nsamp * Cdim) {
        int n = i >> 8, c = i & 255;
        float mu = d_encoded[(size_t)n * H2 + c];
        float lv = d_encoded[(size_t)n * H2 + 256 + c];
        d_zbuf[i] = mu + expf(0.5f * lv) * eps[i];
    }
}

// ---------------- persistent GRU recurrence (one layer) ----------------
// 128 CTAs x 256 threads, 1 unit per warp. whh rows in REGISTERS (96 f/lane).
// h_t loaded straight from global into registers (no smem broadcast, no membar.gl).
// Barrier: lane0 st.cg writes -> syncthreads -> thread0 atom.add.release to one of
// 4 sharded counters -> thread0 acquire-polls the 4 shards -> syncthreads.
__global__ void __launch_bounds__(256, 1)
gru_rec_kernel(const float* __restrict__ whh, const float* __restrict__ bhh,
               const float* __restrict__ gx, float* __restrict__ y, int layer) {
    const int tid = threadIdx.x;
    const int warp = tid >> 5, lane = tid & 31;
    const int u = blockIdx.x * UPC + warp;

    // whh rows (r,z,n) for unit u -> registers. lane l owns cols k = 4l + 128j.
    float4 wr[8], wz[8], wn[8];
#pragma unroll
    for (int j = 0; j < 8; j++) {
        int k = 4 * lane + 128 * j;
        wr[j] = __ldg((const float4*)(whh + (size_t)(0 * Hdim + u) * Hdim + k));
        wz[j] = __ldg((const float4*)(whh + (size_t)(1 * Hdim + u) * Hdim + k));
        wn[j] = __ldg((const float4*)(whh + (size_t)(2 * Hdim + u) * Hdim + k));
    }
    const float br = bhh[u], bz = bhh[Hdim + u], bn = bhh[2 * Hdim + u];
    unsigned (*cnt)[32] = g_cnt + (size_t)layer * Tlen;
    const int myshard = (blockIdx.x & 3) * 8;
    // prefetch input gates for t=0
    float gxr = __ldg(gx + u), gxz = __ldg(gx + Hdim + u), gxn = __ldg(gx + 2 * Hdim + u);
    const unsigned G = gridDim.x;
    float hp = 0.0f;                          // unit u's previous h (lane0-carried)

    for (int t = 0; t < Tlen; ++t) {
        // h_t directly into registers (L2, coalesced 512B/warp per j)
        const float4* hb = (const float4*)g_h[t & 1];
        float4 hv[8];
#pragma unroll
        for (int j = 0; j < 8; ++j) hv[j] = __ldcg(hb + lane + 32 * j);

        float sr = 0.f, sz = 0.f, sn = 0.f;
#pragma unroll
        for (int j = 0; j < 8; ++j) {
            sr += wr[j].x * hv[j].x + wr[j].y * hv[j].y + wr[j].z * hv[j].z + wr[j].w * hv[j].w;
            sz += wz[j].x * hv[j].x + wz[j].y * hv[j].y + wz[j].z * hv[j].z + wz[j].w * hv[j].w;
            sn += wn[j].x * hv[j].x + wn[j].y * hv[j].y + wn[j].z * hv[j].z + wn[j].w * hv[j].w;
        }
#pragma unroll
        for (int o = 16; o > 0; o >>= 1) {
            sr += __shfl_xor_sync(0xffffffffu, sr, o);
            sz += __shfl_xor_sync(0xffffffffu, sz, o);
            sn += __shfl_xor_sync(0xffffffffu, sn, o);
        }
        if (lane == 0) {
            float r = sigmoidf_(gxr + sr + br);
            float z = sigmoidf_(gxz + sz + bz);
            float nn = tanhf(gxn + r * (sn + bn));    // r multiplies (Whh.h + bhh_n)
            float hnew = (1.0f - z) * nn + z * hp;
            hp = hnew;
            __stcg(&g_h[(t + 1) & 1][u], hnew);       // double-buffered publish
            y[(size_t)t * Hdim + u] = hnew;
        }
        // prefetch next step's input gates (hides latency behind barrier)
        if (t + 1 < Tlen) {
            const float* gp = gx + (size_t)(t + 1) * G3;
            gxr = __ldg(gp + u); gxz = __ldg(gp + Hdim + u); gxn = __ldg(gp + 2 * Hdim + u);
        }
        __syncthreads();                      // all lane0 publishes done (CTA scope)
        if (tid == 0) {
            atom_add_release(&cnt[t][myshard], 1u);   // publish (gpu scope release)
            for (;;) {
                unsigned s = ld_acquire(&cnt[t][0]) + ld_acquire(&cnt[t][8])
                           + ld_acquire(&cnt[t][16]) + ld_acquire(&cnt[t][24]);
                if (s >= G) break;
            }
        }
        __syncthreads();                      // propagate acquire to whole CTA
    }
}

// ---------------- losses ----------------
__global__ void loss_kernel() {
    int n = blockIdx.x, tid = threadIdx.x;            // 256 threads
    int warp = tid >> 5, lane = tid & 31;
    float sr = 0.f, sw = 0.f;
    for (int i = tid; i < Hdim; i += 256) {
        float s = d_samples[(size_t)n * Hdim + i];
        float a = d_recon[(size_t)n * Hdim + i] - s;
        float b = d_wout[(size_t)n * Hdim + i] - s;
        sr += a * a;
        sw += b * b;
    }
    float mu = d_encoded[(size_t)n * H2 + tid];
    float lv = d_encoded[(size_t)n * H2 + 256 + tid];
    float sk = 1.0f + lv - mu * mu - expf(lv);
    __shared__ float rbuf[24];
#pragma unroll
    for (int o = 16; o > 0; o >>= 1) {
        sr += __shfl_xor_sync(0xffffffffu, sr, o);
        sw += __shfl_xor_sync(0xffffffffu, sw, o);
        sk += __shfl_xor_sync(0xffffffffu, sk, o);
    }
    if (lane == 0) { rbuf[warp] = sr; rbuf[8 + warp] = sw; rbuf[16 + warp] = sk; }
    __syncthreads();
    if (tid == 0) {
        float tr = 0.f, tw = 0.f, tk = 0.f;
        for (int w = 0; w < 8; ++w) { tr += rbuf[w]; tw += rbuf[8 + w]; tk += rbuf[16 + w]; }
        d_toterr[n] = tr * (1.0f / 1024.0f) + 0.1f * tw * (1.0f / 1024.0f)
                    + 0.001f * (-0.5f * tk);
    }
}

__global__ void mean_kernel(float* __restrict__ out) {
    int tid = threadIdx.x;                            // 256
    int warp = tid >> 5, lane = tid & 31;
    float s = 0.f;
    for (int i = tid; i < Nsamp; i += 256) s += d_toterr[i];
    __shared__ float rbuf[8];
#pragma unroll
    for (int o = 16; o > 0; o >>= 1) s += __shfl_xor_sync(0xffffffffu, s, o);
    if (lane == 0) rbuf[warp] = s;
    __syncthreads();
    if (tid == 0) {
        float t = 0.f;
        for (int w = 0; w < 8; ++w) t += rbuf[w];
        out[0] = t * (1.0f / (float)Nsamp);
    }
}

__global__ void copy_imp_kernel(const float* __restrict__ imp, float* __restrict__ out) {
    int i = blockIdx.x * blockDim.x + threadIdx.x;
    if (i < Msize) out[1 + i] = imp[i];
}

// duplicate indices: last occurrence in idx order wins (serial scatter semantics)
__global__ void scatter_kernel(const int* __restrict__ idx, const float* __restrict__ imp,
                               float* __restrict__ out) {
    int i = blockIdx.x * blockDim.x + threadIdx.x;
    if (i < Nsamp) {
        int d = idx[i];
        bool last = true;
        for (int j = i + 1; j < Nsamp; ++j)
            if (idx[j] == d) { last = false; break; }
        if (last) out[1 + d] = 0.9f * imp[d] + 0.1f * d_toterr[i];
    }
}

// ---------------- launch ----------------
extern "C" void kernel_launch(void* const* d_in, const int* in_sizes, int n_in,
                              void* d_out, int out_size) {
    (void)n_in; (void)out_size;
    const float *episodic, *memimp, *eps;
    const int* idx;
    const float *enc_w1, *enc_b1, *enc_g, *enc_beta, *enc_w2, *enc_b2;
    const float *dec_w1, *dec_b1, *dec_g, *dec_beta, *dec_w2, *dec_b2;
    const float *wih0, *whh0, *bih0, *bhh0, *wih1, *whh1, *bih1, *bhh1;

    if (in_sizes[3] == Nsamp) {
        episodic = (const float*)d_in[0];  memimp = (const float*)d_in[1];
        eps = (const float*)d_in[2];       idx = (const int*)d_in[3];
        enc_w1 = (const float*)d_in[4];    enc_b1 = (const float*)d_in[5];
        enc_g = (const float*)d_in[6];     enc_beta = (const float*)d_in[7];
        enc_w2 = (const float*)d_in[8];    enc_b2 = (const float*)d_in[9];
        dec_w1 = (const float*)d_in[10];   dec_b1 = (const float*)d_in[11];
        dec_g = (const float*)d_in[12];    dec_beta = (const float*)d_in[13];
        dec_w2 = (const float*)d_in[14];   dec_b2 = (const float*)d_in[15];
        wih0 = (const float*)d_in[16];     whh0 = (const float*)d_in[17];
        bih0 = (const float*)d_in[18];     bhh0 = (const float*)d_in[19];
        wih1 = (const float*)d_in[20];     whh1 = (const float*)d_in[21];
        bih1 = (const float*)d_in[22];     bhh1 = (const float*)d_in[23];
    } else {
        episodic = (const float*)d_in[0];  memimp = (const float*)d_in[1];
        eps = (const float*)d_in[2];
        enc_w1 = (const float*)d_in[3];    enc_b1 = (const float*)d_in[4];
        enc_g = (const float*)d_in[5];     enc_beta = (const float*)d_in[6];
        enc_w2 = (const float*)d_in[7];    enc_b2 = (const float*)d_in[8];
        dec_w1 = (const float*)d_in[9];    dec_b1 = (const float*)d_in[10];
        dec_g = (const float*)d_in[11];    dec_beta = (const float*)d_in[12];
        dec_w2 = (const float*)d_in[13];   dec_b2 = (const float*)d_in[14];
        wih0 = (const float*)d_in[15];     whh0 = (const float*)d_in[16];
        bih0 = (const float*)d_in[17];     bhh0 = (const float*)d_in[18];
        wih1 = (const float*)d_in[19];     whh1 = (const float*)d_in[20];
        bih1 = (const float*)d_in[21];     bhh1 = (const float*)d_in[22];
        idx = (const int*)d_in[23];
    }
    float* out = (float*)d_out;

    float *p_samples, *p_e1, *p_encoded, *p_z, *p_d1, *p_recon, *p_gx, *p_y1, *p_wout;
    cudaGetSymbolAddress((void**)&p_samples, d_samples);
    cudaGetSymbolAddress((void**)&p_e1, d_e1);
    cudaGetSymbolAddress((void**)&p_encoded, d_encoded);
    cudaGetSymbolAddress((void**)&p_z, d_zbuf);
    cudaGetSymbolAddress((void**)&p_d1, d_d1);
    cudaGetSymbolAddress((void**)&p_recon, d_recon);
    cudaGetSymbolAddress((void**)&p_gx, d_gx);
    cudaGetSymbolAddress((void**)&p_y1, d_y1);
    cudaGetSymbolAddress((void**)&p_wout, d_wout);

    init_kernel<<<256, 256>>>();
    gather_kernel<<<Nsamp, 256>>>(episodic, idx);

    // encoder
    sgemm_bias_kernel<<<dim3(H2 / BN, Nsamp / BM), 256>>>(p_samples, enc_w1, enc_b1, p_e1,
                                                          Nsamp, H2, Hdim);
    ln_gelu_kernel<<<Nsamp, 128>>>(p_e1, enc_g, enc_beta);
    sgemm_bias_kernel<<<dim3(H2 / BN, Nsamp / BM), 256>>>(p_e1, enc_w2, enc_b2, p_encoded,
                                                          Nsamp, H2, H2);
    reparam_kernel<<<(Nsamp * Cdim) / 256, 256>>>(eps);

    // decoder
    sgemm_bias_kernel<<<dim3(H2 / BN, Nsamp / BM), 256>>>(p_z, dec_w1, dec_b1, p_d1,
                                                          Nsamp, H2, Cdim);
    ln_gelu_kernel<<<Nsamp, 128>>>(p_d1, dec_g, dec_beta);
    sgemm_bias_kernel<<<dim3(Hdim / BN, Nsamp / BM), 256>>>(p_d1, dec_w2, dec_b2, p_recon,
                                                            Nsamp, Hdim, H2);

    // GRU layer 0
    sgemm_bias_kernel<<<dim3(G3 / BN, Nsamp / BM), 256>>>(p_recon, wih0, bih0, p_gx,
                                                          Nsamp, G3, Hdim);
    gru_rec_kernel<<<REC_CTAS, 256>>>(whh0, bhh0, p_gx, p_y1, 0);

    // GRU layer 1
    sgemm_bias_kernel<<<dim3(G3 / BN, Nsamp / BM), 256>>>(p_y1, wih1, bih1, p_gx,
                                                          Nsamp, G3, Hdim);
    zero_h_kernel<<<4, 256>>>();
    gru_rec_kernel<<<REC_CTAS, 256>>>(whh1, bhh1, p_gx, p_wout, 1);

    // losses + outputs
    loss_kernel<<<Nsamp, 256>>>();
    mean_kernel<<<1, 256>>>(out);
    copy_imp_kernel<<<(Msize + 255) / 256, 256>>>(memimp, out);
    scatter_kernel<<<4, 256>>>(idx, memimp, out);
}

// round 7
// speedup vs baseline: 1.4122x; 1.4122x over previous
#include <cuda_runtime.h>
#include <math.h>

#define Hdim   1024
#define H2     512
#define Cdim   256
#define Msize  100000
#define Nsamp  1024
#define Tlen   1024
#define G3     3072
#define REC_CTAS 128
#define UPC    8            // hidden units per CTA (one per warp)
#define NSHARD 8            // barrier counter shards (128B apart)

// ---------------- scratch (static __device__, no allocs) ----------------
__device__ __align__(16) float d_samples[Nsamp * Hdim];
__device__ __align__(16) float d_e1[Nsamp * H2];
__device__ __align__(16) float d_encoded[Nsamp * H2];
__device__ __align__(16) float d_zbuf[Nsamp * Cdim];
__device__ __align__(16) float d_d1[Nsamp * H2];
__device__ __align__(16) float d_recon[Nsamp * Hdim];
__device__ __align__(16) float d_gx[Tlen * G3];
__device__ __align__(16) float d_y1[Tlen * Hdim];
__device__ __align__(16) float d_wout[Tlen * Hdim];
__device__ float d_toterr[Nsamp];
__device__ __align__(16) float g_h[2][Hdim];
// 8-sharded per-step counters, shards 32 u32 (=128B) apart
__device__ __align__(128) unsigned g_cnt[2][Tlen][NSHARD * 32];

__device__ __forceinline__ float gelu_exact(float x) {
    return 0.5f * x * (1.0f + erff(x * 0.7071067811865476f));
}
__device__ __forceinline__ float sigmoidf_(float x) {
    return 1.0f / (1.0f + expf(-x));
}

// ---------------- init / small utility kernels ----------------
__global__ void init_kernel() {
    int i = blockIdx.x * blockDim.x + threadIdx.x;    // 2048 x 256 = 524288
    if (i < 2 * Tlen * NSHARD * 32) ((unsigned*)g_cnt)[i] = 0u;
    if (i < 2 * Hdim) ((float*)g_h)[i] = 0.0f;
}

__global__ void zero_h_kernel() {
    int i = blockIdx.x * blockDim.x + threadIdx.x;
    if (i < Hdim) g_h[0][i] = 0.0f;
}

__global__ void gather_kernel(const float* __restrict__ mem, const int* __restrict__ idx) {
    int n = blockIdx.x;                               // 1024 blocks, 256 threads
    const float4* src = (const float4*)(mem + (size_t)idx[n] * Hdim);
    float4* dst = (float4*)(d_samples + (size_t)n * Hdim);
    dst[threadIdx.x] = src[threadIdx.x];
}

// ---------------- SGEMM: C[M,N] = A[M,K] @ W[N,K]^T + bias ----------------
#define BM 64
#define BN 64
#define BK 16
__global__ void sgemm_bias_kernel(const float* __restrict__ A, const float* __restrict__ W,
                                  const float* __restrict__ bias, float* __restrict__ C,
                                  int M, int N, int K) {
    __shared__ float As[BK][BM + 4];
    __shared__ float Bs[BK][BN + 4];
    const int tid = threadIdx.x;                      // 256
    const int tx = tid & 15, ty = tid >> 4;
    const int row0 = blockIdx.y * BM, col0 = blockIdx.x * BN;
    const int lm = tid >> 2, lk = (tid & 3) * 4;
    const float* Ap = A + (size_t)(row0 + lm) * K + lk;
    const float* Wp = W + (size_t)(col0 + lm) * K + lk;
    float acc[4][4];
#pragma unroll
    for (int i = 0; i < 4; i++)
#pragma unroll
        for (int j = 0; j < 4; j++) acc[i][j] = 0.0f;

    for (int k0 = 0; k0 < K; k0 += BK) {
        float4 a = *(const float4*)(Ap + k0);
        float4 w = *(const float4*)(Wp + k0);
        __syncthreads();
        As[lk + 0][lm] = a.x; As[lk + 1][lm] = a.y; As[lk + 2][lm] = a.z; As[lk + 3][lm] = a.w;
        Bs[lk + 0][lm] = w.x; Bs[lk + 1][lm] = w.y; Bs[lk + 2][lm] = w.z; Bs[lk + 3][lm] = w.w;
        __syncthreads();
#pragma unroll
        for (int k = 0; k < BK; k++) {
            float4 av = *(const float4*)&As[k][ty * 4];
            float4 bv = *(const float4*)&Bs[k][tx * 4];
            acc[0][0] += av.x * bv.x; acc[0][1] += av.x * bv.y; acc[0][2] += av.x * bv.z; acc[0][3] += av.x * bv.w;
            acc[1][0] += av.y * bv.x; acc[1][1] += av.y * bv.y; acc[1][2] += av.y * bv.z; acc[1][3] += av.y * bv.w;
            acc[2][0] += av.z * bv.x; acc[2][1] += av.z * bv.y; acc[2][2] += av.z * bv.z; acc[2][3] += av.z * bv.w;
            acc[3][0] += av.w * bv.x; acc[3][1] += av.w * bv.y; acc[3][2] += av.w * bv.z; acc[3][3] += av.w * bv.w;
        }
    }
    float b0 = bias[col0 + tx * 4 + 0];
    float b1 = bias[col0 + tx * 4 + 1];
    float b2 = bias[col0 + tx * 4 + 2];
    float b3 = bias[col0 + tx * 4 + 3];
#pragma unroll
    for (int i = 0; i < 4; i++) {
        float* Cr = C + (size_t)(row0 + ty * 4 + i) * N + col0 + tx * 4;
        Cr[0] = acc[i][0] + b0;
        Cr[1] = acc[i][1] + b1;
        Cr[2] = acc[i][2] + b2;
        Cr[3] = acc[i][3] + b3;
    }
}

// ---------------- LayerNorm(512) + exact GELU, in place ----------------
__global__ void ln_gelu_kernel(float* __restrict__ x, const float* __restrict__ g,
                               const float* __restrict__ b) {
    int row = blockIdx.x, tid = threadIdx.x;          // 128 threads, 4 elems each
    float4* xr = (float4*)(x + (size_t)row * H2);
    float4 v = xr[tid];
    float s = v.x + v.y + v.z + v.w;
    __shared__ float red[8];
#pragma unroll
    for (int o = 16; o > 0; o >>= 1) s += __shfl_xor_sync(0xffffffffu, s, o);
    if ((tid & 31) == 0) red[tid >> 5] = s;
    __syncthreads();
    float mean = (red[0] + red[1] + red[2] + red[3]) * (1.0f / 512.0f);
    float dx = v.x - mean, dy = v.y - mean, dz = v.z - mean, dw = v.w - mean;
    float q = dx * dx + dy * dy + dz * dz + dw * dw;
#pragma unroll
    for (int o = 16; o > 0; o >>= 1) q += __shfl_xor_sync(0xffffffffu, q, o);
    if ((tid & 31) == 0) red[4 + (tid >> 5)] = q;
    __syncthreads();
    float var = (red[4] + red[5] + red[6] + red[7]) * (1.0f / 512.0f);
    float rstd = rsqrtf(var + 1e-5f);
    float4 gg = ((const float4*)g)[tid];
    float4 bb = ((const float4*)b)[tid];
    v.x = gelu_exact(dx * rstd * gg.x + bb.x);
    v.y = gelu_exact(dy * rstd * gg.y + bb.y);
    v.z = gelu_exact(dz * rstd * gg.z + bb.z);
    v.w = gelu_exact(dw * rstd * gg.w + bb.w);
    xr[tid] = v;
}

// ---------------- reparameterize ----------------
__global__ void reparam_kernel(const float* __restrict__ eps) {
    int i = blockIdx.x * blockDim.x + threadIdx.x;    // N*C = 262144
    if (i < Nsamp * Cdim) {
        int n = i >> 8, c = i & 255;
        float mu = d_encoded[(size_t)n * H2 + c];
        float lv = d_encoded[(size_t)n * H2 + 256 + c];
        d_zbuf[i] = mu + expf(0.5f * lv) * eps[i];
    }
}

// ---------------- persistent GRU recurrence (one layer) ----------------
// 128 CTAs x 256 threads, 1 unit per warp. whh rows in REGISTERS (96 f/lane).
// R4 structure; ONLY the barrier counter is sharded 8x (shards 128B apart) and
// warp 0 polls all 8 shards with one warp-wide volatile LDG + REDUX sum.
__global__ void __launch_bounds__(256, 1)
gru_rec_kernel(const float* __restrict__ whh, const float* __restrict__ bhh,
               const float* __restrict__ gx, float* __restrict__ y, int layer) {
    __shared__ float h_s[Hdim];
    const int tid = threadIdx.x;
    const int warp = tid >> 5, lane = tid & 31;
    const int u = blockIdx.x * UPC + warp;

    // whh rows (r,z,n) for unit u -> registers. lane l owns cols k = 4l + 128j.
    float4 wr[8], wz[8], wn[8];
#pragma unroll
    for (int j = 0; j < 8; j++) {
        int k = 4 * lane + 128 * j;
        wr[j] = __ldg((const float4*)(whh + (size_t)(0 * Hdim + u) * Hdim + k));
        wz[j] = __ldg((const float4*)(whh + (size_t)(1 * Hdim + u) * Hdim + k));
        wn[j] = __ldg((const float4*)(whh + (size_t)(2 * Hdim + u) * Hdim + k));
    }
    const float br = bhh[u], bz = bhh[Hdim + u], bn = bhh[2 * Hdim + u];
    const int myshard = (blockIdx.x & (NSHARD - 1)) * 32;
    // prefetch input gates for t=0
    float gxr = __ldg(gx + u), gxz = __ldg(gx + Hdim + u), gxn = __ldg(gx + 2 * Hdim + u);
    const unsigned G = gridDim.x;

    for (int t = 0; t < Tlen; ++t) {
        // broadcast h_t into smem (L1-bypassing load; written by other SMs last step)
        {
            float4 v = __ldcg(((const float4*)g_h[t & 1]) + tid);
            *(float4*)(h_s + tid * 4) = v;
        }
        __syncthreads();
        float sr = 0.f, sz = 0.f, sn = 0.f;
#pragma unroll
        for (int j = 0; j < 8; ++j) {
            float4 h4 = ((const float4*)h_s)[lane + 32 * j];
            sr += wr[j].x * h4.x + wr[j].y * h4.y + wr[j].z * h4.z + wr[j].w * h4.w;
            sz += wz[j].x * h4.x + wz[j].y * h4.y + wz[j].z * h4.z + wz[j].w * h4.w;
            sn += wn[j].x * h4.x + wn[j].y * h4.y + wn[j].z * h4.z + wn[j].w * h4.w;
        }
#pragma unroll
        for (int o = 16; o > 0; o >>= 1) {
            sr += __shfl_xor_sync(0xffffffffu, sr, o);
            sz += __shfl_xor_sync(0xffffffffu, sz, o);
            sn += __shfl_xor_sync(0xffffffffu, sn, o);
        }
        if (lane == 0) {
            float r = sigmoidf_(gxr + sr + br);
            float z = sigmoidf_(gxz + sz + bz);
            float nn = tanhf(gxn + r * (sn + bn));    // r multiplies (Whh.h + bhh_n)
            float hp = h_s[u];
            float hnew = (1.0f - z) * nn + z * hp;
            g_h[(t + 1) & 1][u] = hnew;               // double-buffered
            y[(size_t)t * Hdim + u] = hnew;
        }
        // prefetch next step's input gates (hides latency behind barrier)
        if (t + 1 < Tlen) {
            const float* gp = gx + (size_t)(t + 1) * G3;
            gxr = __ldg(gp + u); gxz = __ldg(gp + Hdim + u); gxn = __ldg(gp + 2 * Hdim + u);
        }
        __threadfence();
        __syncthreads();
        if (tid < 32) {
            unsigned* c = g_cnt[layer][t];
            if (lane == 0) atomicAdd(c + myshard, 1u);    // <=16 atomics per shard
            unsigned s;
            do {
                unsigned v = (lane < NSHARD) ? *(volatile unsigned*)(c + lane * 32) : 0u;
                s = __reduce_add_sync(0xffffffffu, v);    // REDUX across 8 shards
            } while (s < G);
            __threadfence();
        }
        __syncthreads();
    }
}

// ---------------- losses ----------------
__global__ void loss_kernel() {
    int n = blockIdx.x, tid = threadIdx.x;            // 256 threads
    int warp = tid >> 5, lane = tid & 31;
    float sr = 0.f, sw = 0.f;
    for (int i = tid; i < Hdim; i += 256) {
        float s = d_samples[(size_t)n * Hdim + i];
        float a = d_recon[(size_t)n * Hdim + i] - s;
        float b = d_wout[(size_t)n * Hdim + i] - s;
        sr += a * a;
        sw += b * b;
    }
    float mu = d_encoded[(size_t)n * H2 + tid];
    float lv = d_encoded[(size_t)n * H2 + 256 + tid];
    float sk = 1.0f + lv - mu * mu - expf(lv);
    __shared__ float rbuf[24];
#pragma unroll
    for (int o = 16; o > 0; o >>= 1) {
        sr += __shfl_xor_sync(0xffffffffu, sr, o);
        sw += __shfl_xor_sync(0xffffffffu, sw, o);
        sk += __shfl_xor_sync(0xffffffffu, sk, o);
    }
    if (lane == 0) { rbuf[warp] = sr; rbuf[8 + warp] = sw; rbuf[16 + warp] = sk; }
    __syncthreads();
    if (tid == 0) {
        float tr = 0.f, tw = 0.f, tk = 0.f;
        for (int w = 0; w < 8; ++w) { tr += rbuf[w]; tw += rbuf[8 + w]; tk += rbuf[16 + w]; }
        d_toterr[n] = tr * (1.0f / 1024.0f) + 0.1f * tw * (1.0f / 1024.0f)
                    + 0.001f * (-0.5f * tk);
    }
}

__global__ void mean_kernel(float* __restrict__ out) {
    int tid = threadIdx.x;                            // 256
    int warp = tid >> 5, lane = tid & 31;
    float s = 0.f;
    for (int i = tid; i < Nsamp; i += 256) s += d_toterr[i];
    __shared__ float rbuf[8];
#pragma unroll
    for (int o = 16; o > 0; o >>= 1) s += __shfl_xor_sync(0xffffffffu, s, o);
    if (lane == 0) rbuf[warp] = s;
    __syncthreads();
    if (tid == 0) {
        float t = 0.f;
        for (int w = 0; w < 8; ++w) t += rbuf[w];
        out[0] = t * (1.0f / (float)Nsamp);
    }
}

__global__ void copy_imp_kernel(const float* __restrict__ imp, float* __restrict__ out) {
    int i = blockIdx.x * blockDim.x + threadIdx.x;
    if (i < Msize) out[1 + i] = imp[i];
}

// duplicate indices: last occurrence in idx order wins (serial scatter semantics)
__global__ void scatter_kernel(const int* __restrict__ idx, const float* __restrict__ imp,
                               float* __restrict__ out) {
    int i = blockIdx.x * blockDim.x + threadIdx.x;
    if (i < Nsamp) {
        int d = idx[i];
        bool last = true;
        for (int j = i + 1; j < Nsamp; ++j)
            if (idx[j] == d) { last = false; break; }
        if (last) out[1 + d] = 0.9f * imp[d] + 0.1f * d_toterr[i];
    }
}

// ---------------- launch ----------------
extern "C" void kernel_launch(void* const* d_in, const int* in_sizes, int n_in,
                              void* d_out, int out_size) {
    (void)n_in; (void)out_size;
    const float *episodic, *memimp, *eps;
    const int* idx;
    const float *enc_w1, *enc_b1, *enc_g, *enc_beta, *enc_w2, *enc_b2;
    const float *dec_w1, *dec_b1, *dec_g, *dec_beta, *dec_w2, *dec_b2;
    const float *wih0, *whh0, *bih0, *bhh0, *wih1, *whh1, *bih1, *bhh1;

    if (in_sizes[3] == Nsamp) {
        episodic = (const float*)d_in[0];  memimp = (const float*)d_in[1];
        eps = (const float*)d_in[2];       idx = (const int*)d_in[3];
        enc_w1 = (const float*)d_in[4];    enc_b1 = (const float*)d_in[5];
        enc_g = (const float*)d_in[6];     enc_beta = (const float*)d_in[7];
        enc_w2 = (const float*)d_in[8];    enc_b2 = (const float*)d_in[9];
        dec_w1 = (const float*)d_in[10];   dec_b1 = (const float*)d_in[11];
        dec_g = (const float*)d_in[12];    dec_beta = (const float*)d_in[13];
        dec_w2 = (const float*)d_in[14];   dec_b2 = (const float*)d_in[15];
        wih0 = (const float*)d_in[16];     whh0 = (const float*)d_in[17];
        bih0 = (const float*)d_in[18];     bhh0 = (const float*)d_in[19];
        wih1 = (const float*)d_in[20];     whh1 = (const float*)d_in[21];
        bih1 = (const float*)d_in[22];     bhh1 = (const float*)d_in[23];
    } else {
        episodic = (const float*)d_in[0];  memimp = (const float*)d_in[1];
        eps = (const float*)d_in[2];
        enc_w1 = (const float*)d_in[3];    enc_b1 = (const float*)d_in[4];
        enc_g = (const float*)d_in[5];     enc_beta = (const float*)d_in[6];
        enc_w2 = (const float*)d_in[7];    enc_b2 = (const float*)d_in[8];
        dec_w1 = (const float*)d_in[9];    dec_b1 = (const float*)d_in[10];
        dec_g = (const float*)d_in[11];    dec_beta = (const float*)d_in[12];
        dec_w2 = (const float*)d_in[13];   dec_b2 = (const float*)d_in[14];
        wih0 = (const float*)d_in[15];     whh0 = (const float*)d_in[16];
        bih0 = (const float*)d_in[17];     bhh0 = (const float*)d_in[18];
        wih1 = (const float*)d_in[19];     whh1 = (const float*)d_in[20];
        bih1 = (const float*)d_in[21];     bhh1 = (const float*)d_in[22];
        idx = (const int*)d_in[23];
    }
    float* out = (float*)d_out;

    float *p_samples, *p_e1, *p_encoded, *p_z, *p_d1, *p_recon, *p_gx, *p_y1, *p_wout;
    cudaGetSymbolAddress((void**)&p_samples, d_samples);
    cudaGetSymbolAddress((void**)&p_e1, d_e1);
    cudaGetSymbolAddress((void**)&p_encoded, d_encoded);
    cudaGetSymbolAddress((void**)&p_z, d_zbuf);
    cudaGetSymbolAddress((void**)&p_d1, d_d1);
    cudaGetSymbolAddress((void**)&p_recon, d_recon);
    cudaGetSymbolAddress((void**)&p_gx, d_gx);
    cudaGetSymbolAddress((void**)&p_y1, d_y1);
    cudaGetSymbolAddress((void**)&p_wout, d_wout);

    init_kernel<<<2048, 256>>>();
    gather_kernel<<<Nsamp, 256>>>(episodic, idx);

    // encoder
    sgemm_bias_kernel<<<dim3(H2 / BN, Nsamp / BM), 256>>>(p_samples, enc_w1, enc_b1, p_e1,
                                                          Nsamp, H2, Hdim);
    ln_gelu_kernel<<<Nsamp, 128>>>(p_e1, enc_g, enc_beta);
    sgemm_bias_kernel<<<dim3(H2 / BN, Nsamp / BM), 256>>>(p_e1, enc_w2, enc_b2, p_encoded,
                                                          Nsamp, H2, H2);
    reparam_kernel<<<(Nsamp * Cdim) / 256, 256>>>(eps);

    // decoder
    sgemm_bias_kernel<<<dim3(H2 / BN, Nsamp / BM), 256>>>(p_z, dec_w1, dec_b1, p_d1,
                                                          Nsamp, H2, Cdim);
    ln_gelu_kernel<<<Nsamp, 128>>>(p_d1, dec_g, dec_beta);
    sgemm_bias_kernel<<<dim3(Hdim / BN, Nsamp / BM), 256>>>(p_d1, dec_w2, dec_b2, p_recon,
                                                            Nsamp, Hdim, H2);

    // GRU layer 0
    sgemm_bias_kernel<<<dim3(G3 / BN, Nsamp / BM), 256>>>(p_recon, wih0, bih0, p_gx,
                                                          Nsamp, G3, Hdim);
    gru_rec_kernel<<<REC_CTAS, 256>>>(whh0, bhh0, p_gx, p_y1, 0);

    // GRU layer 1
    sgemm_bias_kernel<<<dim3(G3 / BN, Nsamp / BM), 256>>>(p_y1, wih1, bih1, p_gx,
                                                          Nsamp, G3, Hdim);
    zero_h_kernel<<<4, 256>>>();
    gru_rec_kernel<<<REC_CTAS, 256>>>(whh1, bhh1, p_gx, p_wout, 1);

    // losses + outputs
    loss_kernel<<<Nsamp, 256>>>();
    mean_kernel<<<1, 256>>>(out);
    copy_imp_kernel<<<(Msize + 255) / 256, 256>>>(memimp, out);
    scatter_kernel<<<4, 256>>>(idx, memimp, out);
}

// round 8
// speedup vs baseline: 1.5853x; 1.1226x over previous
#include <cuda_runtime.h>
#include <math.h>

#define Hdim   1024
#define H2     512
#define Cdim   256
#define Msize  100000
#define Nsamp  1024
#define Tlen   1024
#define G3     3072
#define REC_CTAS 128
#define UPC    8            // hidden units per CTA (one per warp)

// ---------------- scratch (static __device__, no allocs) ----------------
__device__ __align__(16) float d_samples[Nsamp * Hdim];
__device__ __align__(16) float d_e1[Nsamp * H2];
__device__ __align__(16) float d_encoded[Nsamp * H2];
__device__ __align__(16) float d_zbuf[Nsamp * Cdim];
__device__ __align__(16) float d_d1[Nsamp * H2];
__device__ __align__(16) float d_recon[Nsamp * Hdim];
__device__ __align__(16) float d_gx[Tlen * G3];
__device__ __align__(16) float d_y1[Tlen * Hdim];
__device__ __align__(16) float d_wout[Tlen * Hdim];
__device__ float d_toterr[Nsamp];
__device__ __align__(16) float g_h[2][Hdim];
__device__ unsigned g_counts[2 * Tlen];

__device__ __forceinline__ float gelu_exact(float x) {
    return 0.5f * x * (1.0f + erff(x * 0.7071067811865476f));
}
__device__ __forceinline__ float sigmoidf_(float x) {
    return 1.0f / (1.0f + expf(-x));
}
__device__ __forceinline__ void red_add_release(unsigned* p, unsigned v) {
    asm volatile("red.add.release.gpu.global.u32 [%0], %1;" :: "l"(p), "r"(v) : "memory");
}
__device__ __forceinline__ unsigned ld_acquire(const unsigned* p) {
    unsigned v;
    asm volatile("ld.acquire.gpu.global.u32 %0, [%1];" : "=r"(v) : "l"(p) : "memory");
    return v;
}

// ---------------- init / small utility kernels ----------------
__global__ void init_kernel() {
    int i = blockIdx.x * blockDim.x + threadIdx.x;    // 8 x 256 = 2048
    if (i < 2 * Tlen) g_counts[i] = 0u;
    if (i < 2 * Hdim) ((float*)g_h)[i] = 0.0f;
}

__global__ void zero_h_kernel() {
    int i = blockIdx.x * blockDim.x + threadIdx.x;
    if (i < Hdim) g_h[0][i] = 0.0f;
}

__global__ void gather_kernel(const float* __restrict__ mem, const int* __restrict__ idx) {
    int n = blockIdx.x;                               // 1024 blocks, 256 threads
    const float4* src = (const float4*)(mem + (size_t)idx[n] * Hdim);
    float4* dst = (float4*)(d_samples + (size_t)n * Hdim);
    dst[threadIdx.x] = src[threadIdx.x];
}

// ---------------- SGEMM 128x128x8, double-buffered: C = A@W^T + bias -------
// A[M,K], W[N,K], C[M,N]. 256 threads, 8x8 acc/thread, 1 syncthreads/iter.
#define TBM 128
#define TBN 128
#define TBK 8
__global__ void __launch_bounds__(256)
sgemm_bias_kernel(const float* __restrict__ A, const float* __restrict__ W,
                  const float* __restrict__ bias, float* __restrict__ C,
                  int M, int N, int K) {
    __shared__ float As[2][TBK][TBM];
    __shared__ float Bs[2][TBK][TBN];
    const int tid = threadIdx.x;                      // 256
    const int tx = tid & 15, ty = tid >> 4;
    const int row0 = blockIdx.y * TBM, col0 = blockIdx.x * TBN;
    const int lr = tid >> 1;                          // 0..127
    const int lk = (tid & 1) * 4;                     // 0 or 4
    const float* Ap = A + (size_t)(row0 + lr) * K + lk;
    const float* Wp = W + (size_t)(col0 + lr) * K + lk;

    // stage 0
    {
        float4 a = *(const float4*)Ap;
        float4 b = *(const float4*)Wp;
        As[0][lk + 0][lr] = a.x; As[0][lk + 1][lr] = a.y;
        As[0][lk + 2][lr] = a.z; As[0][lk + 3][lr] = a.w;
        Bs[0][lk + 0][lr] = b.x; Bs[0][lk + 1][lr] = b.y;
        Bs[0][lk + 2][lr] = b.z; Bs[0][lk + 3][lr] = b.w;
    }
    __syncthreads();

    float acc[8][8];
#pragma unroll
    for (int i = 0; i < 8; i++)
#pragma unroll
        for (int j = 0; j < 8; j++) acc[i][j] = 0.0f;

    const int nIter = K / TBK;
    int cur = 0;
    for (int it = 0; it < nIter; ++it) {
        float4 an, bn;
        const bool more = (it + 1 < nIter);
        if (more) {
            an = *(const float4*)(Ap + (it + 1) * TBK);
            bn = *(const float4*)(Wp + (it + 1) * TBK);
        }
#pragma unroll
        for (int k = 0; k < TBK; k++) {
            float af[8], bf[8];
            *(float4*)&af[0] = *(const float4*)&As[cur][k][ty * 8];
            *(float4*)&af[4] = *(const float4*)&As[cur][k][ty * 8 + 4];
            *(float4*)&bf[0] = *(const float4*)&Bs[cur][k][tx * 8];
            *(float4*)&bf[4] = *(const float4*)&Bs[cur][k][tx * 8 + 4];
#pragma unroll
            for (int i = 0; i < 8; i++)
#pragma unroll
                for (int j = 0; j < 8; j++) acc[i][j] += af[i] * bf[j];
        }
        if (more) {
            int nxt = cur ^ 1;
            As[nxt][lk + 0][lr] = an.x; As[nxt][lk + 1][lr] = an.y;
            As[nxt][lk + 2][lr] = an.z; As[nxt][lk + 3][lr] = an.w;
            Bs[nxt][lk + 0][lr] = bn.x; Bs[nxt][lk + 1][lr] = bn.y;
            Bs[nxt][lk + 2][lr] = bn.z; Bs[nxt][lk + 3][lr] = bn.w;
            __syncthreads();
            cur = nxt;
        }
    }

    float bc[8];
#pragma unroll
    for (int j = 0; j < 8; j++) bc[j] = bias[col0 + tx * 8 + j];
#pragma unroll
    for (int i = 0; i < 8; i++) {
        float* Cr = C + (size_t)(row0 + ty * 8 + i) * N + col0 + tx * 8;
        float4 v0 = make_float4(acc[i][0] + bc[0], acc[i][1] + bc[1],
                                acc[i][2] + bc[2], acc[i][3] + bc[3]);
        float4 v1 = make_float4(acc[i][4] + bc[4], acc[i][5] + bc[5],
                                acc[i][6] + bc[6], acc[i][7] + bc[7]);
        *(float4*)Cr = v0;
        *(float4*)(Cr + 4) = v1;
    }
}

// ---------------- LayerNorm(512) + exact GELU, in place ----------------
__global__ void ln_gelu_kernel(float* __restrict__ x, const float* __restrict__ g,
                               const float* __restrict__ b) {
    int row = blockIdx.x, tid = threadIdx.x;          // 128 threads, 4 elems each
    float4* xr = (float4*)(x + (size_t)row * H2);
    float4 v = xr[tid];
    float s = v.x + v.y + v.z + v.w;
    __shared__ float red[8];
#pragma unroll
    for (int o = 16; o > 0; o >>= 1) s += __shfl_xor_sync(0xffffffffu, s, o);
    if ((tid & 31) == 0) red[tid >> 5] = s;
    __syncthreads();
    float mean = (red[0] + red[1] + red[2] + red[3]) * (1.0f / 512.0f);
    float dx = v.x - mean, dy = v.y - mean, dz = v.z - mean, dw = v.w - mean;
    float q = dx * dx + dy * dy + dz * dz + dw * dw;
#pragma unroll
    for (int o = 16; o > 0; o >>= 1) q += __shfl_xor_sync(0xffffffffu, q, o);
    if ((tid & 31) == 0) red[4 + (tid >> 5)] = q;
    __syncthreads();
    float var = (red[4] + red[5] + red[6] + red[7]) * (1.0f / 512.0f);
    float rstd = rsqrtf(var + 1e-5f);
    float4 gg = ((const float4*)g)[tid];
    float4 bb = ((const float4*)b)[tid];
    v.x = gelu_exact(dx * rstd * gg.x + bb.x);
    v.y = gelu_exact(dy * rstd * gg.y + bb.y);
    v.z = gelu_exact(dz * rstd * gg.z + bb.z);
    v.w = gelu_exact(dw * rstd * gg.w + bb.w);
    xr[tid] = v;
}

// ---------------- reparameterize ----------------
__global__ void reparam_kernel(const float* __restrict__ eps) {
    int i = blockIdx.x * blockDim.x + threadIdx.x;    // N*C = 262144
    if (i < Nsamp * Cdim) {
        int n = i >> 8, c = i & 255;
        float mu = d_encoded[(size_t)n * H2 + c];
        float lv = d_encoded[(size_t)n * H2 + 256 + c];
        d_zbuf[i] = mu + expf(0.5f * lv) * eps[i];
    }
}

// ---------------- persistent GRU recurrence (one layer) ----------------
// 128 CTAs x 256 threads, 1 unit per warp. whh rows in REGISTERS (96 f/lane).
// R4 structure; barrier fences replaced by release/acquire at the counter:
// lane0 h-stores -> syncthreads (CTA HB) -> thread0 red.add.release.gpu ->
// thread0 ld.acquire.gpu spin -> syncthreads (propagate).
__global__ void __launch_bounds__(256, 1)
gru_rec_kernel(const float* __restrict__ whh, const float* __restrict__ bhh,
               const float* __restrict__ gx, float* __restrict__ y, int layer) {
    __shared__ float h_s[Hdim];
    const int tid = threadIdx.x;
    const int warp = tid >> 5, lane = tid & 31;
    const int u = blockIdx.x * UPC + warp;

    // whh rows (r,z,n) for unit u -> registers. lane l owns cols k = 4l + 128j.
    float4 wr[8], wz[8], wn[8];
#pragma unroll
    for (int j = 0; j < 8; j++) {
        int k = 4 * lane + 128 * j;
        wr[j] = __ldg((const float4*)(whh + (size_t)(0 * Hdim + u) * Hdim + k));
        wz[j] = __ldg((const float4*)(whh + (size_t)(1 * Hdim + u) * Hdim + k));
        wn[j] = __ldg((const float4*)(whh + (size_t)(2 * Hdim + u) * Hdim + k));
    }
    const float br = bhh[u], bz = bhh[Hdim + u], bn = bhh[2 * Hdim + u];
    unsigned* counts = g_counts + layer * Tlen;
    // prefetch input gates for t=0
    float gxr = __ldg(gx + u), gxz = __ldg(gx + Hdim + u), gxn = __ldg(gx + 2 * Hdim + u);
    const unsigned G = gridDim.x;

    for (int t = 0; t < Tlen; ++t) {
        // broadcast h_t into smem (L1-bypassing load; written by other SMs last step)
        {
            float4 v = __ldcg(((const float4*)g_h[t & 1]) + tid);
            *(float4*)(h_s + tid * 4) = v;
        }
        __syncthreads();
        float sr = 0.f, sz = 0.f, sn = 0.f;
#pragma unroll
        for (int j = 0; j < 8; ++j) {
            float4 h4 = ((const float4*)h_s)[lane + 32 * j];
            sr += wr[j].x * h4.x + wr[j].y * h4.y + wr[j].z * h4.z + wr[j].w * h4.w;
            sz += wz[j].x * h4.x + wz[j].y * h4.y + wz[j].z * h4.z + wz[j].w * h4.w;
            sn += wn[j].x * h4.x + wn[j].y * h4.y + wn[j].z * h4.z + wn[j].w * h4.w;
        }
#pragma unroll
        for (int o = 16; o > 0; o >>= 1) {
            sr += __shfl_xor_sync(0xffffffffu, sr, o);
            sz += __shfl_xor_sync(0xffffffffu, sz, o);
            sn += __shfl_xor_sync(0xffffffffu, sn, o);
        }
        if (lane == 0) {
            float r = sigmoidf_(gxr + sr + br);
            float z = sigmoidf_(gxz + sz + bz);
            float nn = tanhf(gxn + r * (sn + bn));    // r multiplies (Whh.h + bhh_n)
            float hp = h_s[u];
            float hnew = (1.0f - z) * nn + z * hp;
            g_h[(t + 1) & 1][u] = hnew;               // double-buffered
            y[(size_t)t * Hdim + u] = hnew;
        }
        // prefetch next step's input gates (hides latency behind barrier)
        if (t + 1 < Tlen) {
            const float* gp = gx + (size_t)(t + 1) * G3;
            gxr = __ldg(gp + u); gxz = __ldg(gp + Hdim + u); gxn = __ldg(gp + 2 * Hdim + u);
        }
        __syncthreads();                  // all lane0 publishes done (CTA-scope HB)
        if (tid == 0) {
            red_add_release(counts + t, 1u);          // release: h stores visible
            while (ld_acquire(counts + t) < G) { }    // acquire: peers' h visible
        }
        __syncthreads();                  // propagate acquire to whole CTA
    }
}

// ---------------- losses ----------------
__global__ void loss_kernel() {
    int n = blockIdx.x, tid = threadIdx.x;            // 256 threads
    int warp = tid >> 5, lane = tid & 31;
    float sr = 0.f, sw = 0.f;
    for (int i = tid; i < Hdim; i += 256) {
        float s = d_samples[(size_t)n * Hdim + i];
        float a = d_recon[(size_t)n * Hdim + i] - s;
        float b = d_wout[(size_t)n * Hdim + i] - s;
        sr += a * a;
        sw += b * b;
    }
    float mu = d_encoded[(size_t)n * H2 + tid];
    float lv = d_encoded[(size_t)n * H2 + 256 + tid];
    float sk = 1.0f + lv - mu * mu - expf(lv);
    __shared__ float rbuf[24];
#pragma unroll
    for (int o = 16; o > 0; o >>= 1) {
        sr += __shfl_xor_sync(0xffffffffu, sr, o);
        sw += __shfl_xor_sync(0xffffffffu, sw, o);
        sk += __shfl_xor_sync(0xffffffffu, sk, o);
    }
    if (lane == 0) { rbuf[warp] = sr; rbuf[8 + warp] = sw; rbuf[16 + warp] = sk; }
    __syncthreads();
    if (tid == 0) {
        float tr = 0.f, tw = 0.f, tk = 0.f;
        for (int w = 0; w < 8; ++w) { tr += rbuf[w]; tw += rbuf[8 + w]; tk += rbuf[16 + w]; }
        d_toterr[n] = tr * (1.0f / 1024.0f) + 0.1f * tw * (1.0f / 1024.0f)
                    + 0.001f * (-0.5f * tk);
    }
}

__global__ void mean_kernel(float* __restrict__ out) {
    int tid = threadIdx.x;                            // 256
    int warp = tid >> 5, lane = tid & 31;
    float s = 0.f;
    for (int i = tid; i < Nsamp; i += 256) s += d_toterr[i];
    __shared__ float rbuf[8];
#pragma unroll
    for (int o = 16; o > 0; o >>= 1) s += __shfl_xor_sync(0xffffffffu, s, o);
    if (lane == 0) rbuf[warp] = s;
    __syncthreads();
    if (tid == 0) {
        float t = 0.f;
        for (int w = 0; w < 8; ++w) t += rbuf[w];
        out[0] = t * (1.0f / (float)Nsamp);
    }
}

__global__ void copy_imp_kernel(const float* __restrict__ imp, float* __restrict__ out) {
    int i = blockIdx.x * blockDim.x + threadIdx.x;
    if (i < Msize) out[1 + i] = imp[i];
}

// duplicate indices: last occurrence in idx order wins (serial scatter semantics)
__global__ void scatter_kernel(const int* __restrict__ idx, const float* __restrict__ imp,
                               float* __restrict__ out) {
    int i = blockIdx.x * blockDim.x + threadIdx.x;
    if (i < Nsamp) {
        int d = idx[i];
        bool last = true;
        for (int j = i + 1; j < Nsamp; ++j)
            if (idx[j] == d) { last = false; break; }
        if (last) out[1 + d] = 0.9f * imp[d] + 0.1f * d_toterr[i];
    }
}

// ---------------- launch ----------------
extern "C" void kernel_launch(void* const* d_in, const int* in_sizes, int n_in,
                              void* d_out, int out_size) {
    (void)n_in; (void)out_size;
    const float *episodic, *memimp, *eps;
    const int* idx;
    const float *enc_w1, *enc_b1, *enc_g, *enc_beta, *enc_w2, *enc_b2;
    const float *dec_w1, *dec_b1, *dec_g, *dec_beta, *dec_w2, *dec_b2;
    const float *wih0, *whh0, *bih0, *bhh0, *wih1, *whh1, *bih1, *bhh1;

    if (in_sizes[3] == Nsamp) {
        episodic = (const float*)d_in[0];  memimp = (const float*)d_in[1];
        eps = (const float*)d_in[2];       idx = (const int*)d_in[3];
        enc_w1 = (const float*)d_in[4];    enc_b1 = (const float*)d_in[5];
        enc_g = (const float*)d_in[6];     enc_beta = (const float*)d_in[7];
        enc_w2 = (const float*)d_in[8];    enc_b2 = (const float*)d_in[9];
        dec_w1 = (const float*)d_in[10];   dec_b1 = (const float*)d_in[11];
        dec_g = (const float*)d_in[12];    dec_beta = (const float*)d_in[13];
        dec_w2 = (const float*)d_in[14];   dec_b2 = (const float*)d_in[15];
        wih0 = (const float*)d_in[16];     whh0 = (const float*)d_in[17];
        bih0 = (const float*)d_in[18];     bhh0 = (const float*)d_in[19];
        wih1 = (const float*)d_in[20];     whh1 = (const float*)d_in[21];
        bih1 = (const float*)d_in[22];     bhh1 = (const float*)d_in[23];
    } else {
        episodic = (const float*)d_in[0];  memimp = (const float*)d_in[1];
        eps = (const float*)d_in[2];
        enc_w1 = (const float*)d_in[3];    enc_b1 = (const float*)d_in[4];
        enc_g = (const float*)d_in[5];     enc_beta = (const float*)d_in[6];
        enc_w2 = (const float*)d_in[7];    enc_b2 = (const float*)d_in[8];
        dec_w1 = (const float*)d_in[9];    dec_b1 = (const float*)d_in[10];
        dec_g = (const float*)d_in[11];    dec_beta = (const float*)d_in[12];
        dec_w2 = (const float*)d_in[13];   dec_b2 = (const float*)d_in[14];
        wih0 = (const float*)d_in[15];     whh0 = (const float*)d_in[16];
        bih0 = (const float*)d_in[17];     bhh0 = (const float*)d_in[18];
        wih1 = (const float*)d_in[19];     whh1 = (const float*)d_in[20];
        bih1 = (const float*)d_in[21];     bhh1 = (const float*)d_in[22];
        idx = (const int*)d_in[23];
    }
    float* out = (float*)d_out;

    float *p_samples, *p_e1, *p_encoded, *p_z, *p_d1, *p_recon, *p_gx, *p_y1, *p_wout;
    cudaGetSymbolAddress((void**)&p_samples, d_samples);
    cudaGetSymbolAddress((void**)&p_e1, d_e1);
    cudaGetSymbolAddress((void**)&p_encoded, d_encoded);
    cudaGetSymbolAddress((void**)&p_z, d_zbuf);
    cudaGetSymbolAddress((void**)&p_d1, d_d1);
    cudaGetSymbolAddress((void**)&p_recon, d_recon);
    cudaGetSymbolAddress((void**)&p_gx, d_gx);
    cudaGetSymbolAddress((void**)&p_y1, d_y1);
    cudaGetSymbolAddress((void**)&p_wout, d_wout);

    init_kernel<<<8, 256>>>();
    gather_kernel<<<Nsamp, 256>>>(episodic, idx);

    // encoder
    sgemm_bias_kernel<<<dim3(H2 / TBN, Nsamp / TBM), 256>>>(p_samples, enc_w1, enc_b1, p_e1,
                                                            Nsamp, H2, Hdim);
    ln_gelu_kernel<<<Nsamp, 128>>>(p_e1, enc_g, enc_beta);
    sgemm_bias_kernel<<<dim3(H2 / TBN, Nsamp / TBM), 256>>>(p_e1, enc_w2, enc_b2, p_encoded,
                                                            Nsamp, H2, H2);
    reparam_kernel<<<(Nsamp * Cdim) / 256, 256>>>(eps);

    // decoder
    sgemm_bias_kernel<<<dim3(H2 / TBN, Nsamp / TBM), 256>>>(p_z, dec_w1, dec_b1, p_d1,
                                                            Nsamp, H2, Cdim);
    ln_gelu_kernel<<<Nsamp, 128>>>(p_d1, dec_g, dec_beta);
    sgemm_bias_kernel<<<dim3(Hdim / TBN, Nsamp / TBM), 256>>>(p_d1, dec_w2, dec_b2, p_recon,
                                                              Nsamp, Hdim, H2);

    // GRU layer 0
    sgemm_bias_kernel<<<dim3(G3 / TBN, Nsamp / TBM), 256>>>(p_recon, wih0, bih0, p_gx,
                                                            Nsamp, G3, Hdim);
    gru_rec_kernel<<<REC_CTAS, 256>>>(whh0, bhh0, p_gx, p_y1, 0);

    // GRU layer 1
    sgemm_bias_kernel<<<dim3(G3 / TBN, Nsamp / TBM), 256>>>(p_y1, wih1, bih1, p_gx,
                                                            Nsamp, G3, Hdim);
    zero_h_kernel<<<4, 256>>>();
    gru_rec_kernel<<<REC_CTAS, 256>>>(whh1, bhh1, p_gx, p_wout, 1);

    // losses + outputs
    loss_kernel<<<Nsamp, 256>>>();
    mean_kernel<<<1, 256>>>(out);
    copy_imp_kernel<<<(Msize + 255) / 256, 256>>>(memimp, out);
    scatter_kernel<<<4, 256>>>(idx, memimp, out);
}